// round 10
// baseline (speedup 1.0000x reference)
#include <cuda_runtime.h>
#include <cuda_fp16.h>
#include <cstdint>

// ---------------------------------------------------------------------------
// Problem constants (fixed by the dataset)
// ---------------------------------------------------------------------------
#define N_NODES 100000
#define N_EDGES 1600000
#define D_IN    256
#define D_HID   512
#define D_OUT   48
#define K_STEPS 10
#define ALPHA   0.1f

#define NBLK_NODES ((N_NODES + 255) / 256)   // 391
#define W1_ELEMS  (D_IN * D_HID)             // 131072
#define N_BUCKET  64

// ---------------------------------------------------------------------------
// Scratch (static __device__ arrays; no allocation allowed)
// ---------------------------------------------------------------------------
__device__ __align__(16) __half g_hidh[(size_t)N_NODES * D_HID];  // fp16 hid
__device__ __align__(16) float g_h[(size_t)N_NODES * D_OUT];
__device__ __align__(16) float g_w1r[W1_ELEMS];                   // tf32-rounded W1
__device__ __align__(16) __half2 g_zA[(size_t)N_NODES * (D_OUT / 2)];
__device__ __align__(16) __half2 g_zB[(size_t)N_NODES * (D_OUT / 2)];
__device__ float g_dinv[N_NODES];
__device__ int   g_deg[N_NODES];
__device__ int   g_cursor[N_NODES];
__device__ int   g_rowptr[N_NODES + 1];
__device__ int   g_bsum[NBLK_NODES];
__device__ int   g_bpre[NBLK_NODES];
__device__ int   g_bucket[N_BUCKET];
__device__ int   g_bstart[N_BUCKET];
__device__ int   g_bcur[N_BUCKET];
__device__ int   g_perm[N_NODES];     // nodes sorted by degree (load balance)
__device__ int   g_src[N_EDGES];
__device__ int   g_dst[N_EDGES];
__device__ int   g_csri[N_EDGES];     // CSR: src index only (norm folded into z)

// ---------------------------------------------------------------------------
// mma helpers
// ---------------------------------------------------------------------------
__device__ __forceinline__ uint32_t f2tf32(float f) {
    uint32_t u;
    asm("cvt.rna.tf32.f32 %0, %1;" : "=r"(u) : "f"(f));
    return u;
}

__device__ __forceinline__ void mma_tf32(float* c,
                                         uint32_t a0, uint32_t a1,
                                         uint32_t a2, uint32_t a3,
                                         uint32_t b0, uint32_t b1) {
    asm volatile(
        "mma.sync.aligned.m16n8k8.row.col.f32.tf32.tf32.f32 "
        "{%0,%1,%2,%3}, {%4,%5,%6,%7}, {%8,%9}, {%0,%1,%2,%3};"
        : "+f"(c[0]), "+f"(c[1]), "+f"(c[2]), "+f"(c[3])
        : "r"(a0), "r"(a1), "r"(a2), "r"(a3), "r"(b0), "r"(b1));
}

__device__ __forceinline__ void mma_f16(float* c,
                                        uint32_t a0, uint32_t a1,
                                        uint32_t a2, uint32_t a3,
                                        uint32_t b0, uint32_t b1) {
    asm volatile(
        "mma.sync.aligned.m16n8k16.row.col.f32.f16.f16.f32 "
        "{%0,%1,%2,%3}, {%4,%5,%6,%7}, {%8,%9}, {%0,%1,%2,%3};"
        : "+f"(c[0]), "+f"(c[1]), "+f"(c[2]), "+f"(c[3])
        : "r"(a0), "r"(a1), "r"(a2), "r"(a3), "r"(b0), "r"(b1));
}

#define CP_ASYNC_16(dst_u32, src_ptr) \
    asm volatile("cp.async.cg.shared.global [%0], [%1], 16;" \
                 :: "r"(dst_u32), "l"(src_ptr))
#define CP_COMMIT() asm volatile("cp.async.commit_group;")
#define CP_WAIT(N)  asm volatile("cp.async.wait_group %0;" :: "n"(N))

// ---------------------------------------------------------------------------
// GEMM1: g_hidh = half(relu(x @ W1 + b1)), tf32 tensor cores.
// (structure unchanged from R9; epilogue now stores fp16)
// ---------------------------------------------------------------------------
#define AS_STRIDE 20
#define BS_STRIDE 136
#define AS_STAGE (128 * AS_STRIDE)
#define BS_STAGE (16 * BS_STRIDE)
#define G1_SMEM ((3 * AS_STAGE + 3 * BS_STAGE) * 4)   // 56832 bytes
#define N_CHUNK (D_IN / 16)                 // 16

__global__ __launch_bounds__(256, 2) void gemm1_tc_kernel(
    const float* __restrict__ A,    // [M, 256]
    const float* __restrict__ bias, // [512]
    int M)
{
    extern __shared__ float smem[];
    float* AsB = smem;
    float* BsB = smem + 3 * AS_STAGE;

    const int tid = threadIdx.x;
    const int bn = blockIdx.x * 128;
    const int bm = blockIdx.y * 128;

    const int wid = tid >> 5;
    const int lane = tid & 31;
    const int g = lane >> 2;
    const int t = lane & 3;
    const int wm = wid & 1;
    const int wn = wid >> 1;

    float acc[4][4][4];
#pragma unroll
    for (int i = 0; i < 4; i++)
#pragma unroll
        for (int j = 0; j < 4; j++)
#pragma unroll
            for (int q = 0; q < 4; q++) acc[i][j][q] = 0.0f;

    uint32_t aDst[2], bDst[2];
    const float* aSrc[2];
    const float* bSrc[2];
    {
        const uint32_t asBase = (uint32_t)__cvta_generic_to_shared(AsB);
        const uint32_t bsBase = (uint32_t)__cvta_generic_to_shared(BsB);
#pragma unroll
        for (int q = 0; q < 2; q++) {
            const int idx = tid + 256 * q;
            const int ar = idx >> 2;
            const int ac = (idx & 3) * 4;
            aDst[q] = asBase + (ar * AS_STRIDE + ac) * 4;
            const int gr = min(bm + ar, M - 1);
            aSrc[q] = A + (size_t)gr * D_IN + ac;
            const int br = idx >> 5;
            const int bc = (idx & 31) * 4;
            bDst[q] = bsBase + (br * BS_STRIDE + bc) * 4;
            bSrc[q] = g_w1r + (size_t)br * D_HID + bn + bc;
        }
    }

#pragma unroll
    for (int q = 0; q < 2; q++) {
        CP_ASYNC_16(aDst[q], aSrc[q]);
        CP_ASYNC_16(bDst[q], bSrc[q]);
    }
    CP_COMMIT();
#pragma unroll
    for (int q = 0; q < 2; q++) {
        CP_ASYNC_16(aDst[q] + AS_STAGE * 4, aSrc[q] + 16);
        CP_ASYNC_16(bDst[q] + BS_STAGE * 4, bSrc[q] + (size_t)16 * D_HID);
    }
    CP_COMMIT();

    int stC = 0;
    for (int ch = 0; ch < N_CHUNK; ch++) {
        if (ch < N_CHUNK - 1) { CP_WAIT(1); } else { CP_WAIT(0); }
        __syncthreads();

        const float* As = AsB + stC * AS_STAGE;
        const float* Bs = BsB + stC * BS_STAGE;
#pragma unroll
        for (int ks = 0; ks < 2; ks++) {
            const int kb = ks * 8;
            uint32_t af[4][4], bf[4][2];
#pragma unroll
            for (int i = 0; i < 4; i++) {
                const int m = wm * 64 + i * 16 + g;
                af[i][0] = f2tf32(As[m * AS_STRIDE + kb + t]);
                af[i][1] = f2tf32(As[(m + 8) * AS_STRIDE + kb + t]);
                af[i][2] = f2tf32(As[m * AS_STRIDE + kb + t + 4]);
                af[i][3] = f2tf32(As[(m + 8) * AS_STRIDE + kb + t + 4]);
            }
#pragma unroll
            for (int j = 0; j < 4; j++) {
                const int n = wn * 32 + j * 8 + g;
                bf[j][0] = __float_as_uint(Bs[(kb + t) * BS_STRIDE + n]);
                bf[j][1] = __float_as_uint(Bs[(kb + t + 4) * BS_STRIDE + n]);
            }
#pragma unroll
            for (int i = 0; i < 4; i++)
#pragma unroll
                for (int j = 0; j < 4; j++)
                    mma_tf32(acc[i][j], af[i][0], af[i][1], af[i][2], af[i][3],
                             bf[j][0], bf[j][1]);
        }

        if (ch + 2 < N_CHUNK) {
            const int stP = (stC + 2 >= 3) ? stC - 1 : stC + 2;
            const int ko = (ch + 2) * 16;
#pragma unroll
            for (int q = 0; q < 2; q++) {
                CP_ASYNC_16(aDst[q] + stP * AS_STAGE * 4, aSrc[q] + ko);
                CP_ASYNC_16(bDst[q] + stP * BS_STAGE * 4, bSrc[q] + (size_t)ko * D_HID);
            }
            CP_COMMIT();
        }
        stC = (stC + 1 == 3) ? 0 : stC + 1;
    }

    // epilogue: bias + relu -> fp16 store
#pragma unroll
    for (int i = 0; i < 4; i++) {
        const int r0 = bm + wm * 64 + i * 16 + g;
        const int r1 = r0 + 8;
#pragma unroll
        for (int j = 0; j < 4; j++) {
            const int gc = bn + wn * 32 + j * 8 + 2 * t;
            const float bz0 = __ldg(bias + gc);
            const float bz1 = __ldg(bias + gc + 1);
            if (r0 < M) {
                *(__half2*)(g_hidh + (size_t)r0 * D_HID + gc) =
                    __float22half2_rn(make_float2(fmaxf(acc[i][j][0] + bz0, 0.f),
                                                  fmaxf(acc[i][j][1] + bz1, 0.f)));
            }
            if (r1 < M) {
                *(__half2*)(g_hidh + (size_t)r1 * D_HID + gc) =
                    __float22half2_rn(make_float2(fmaxf(acc[i][j][2] + bz0, 0.f),
                                                  fmaxf(acc[i][j][3] + bz1, 0.f)));
            }
        }
    }
}

// ---------------------------------------------------------------------------
// GEMM2: h = hid(fp16) @ W2 + b2, fp16 m16n8k16 mma, fp32 accum.
// 256 threads (8 warps, 4M x 2N), bm=128, BK=32 (2 k-steps per chunk).
// A smem [m][k] stride 40 halves; B smem transposed [n][k] stride 40.
// Epilogue: g_h = h (fp32); zbuf = half2(dinv * h).
// ---------------------------------------------------------------------------
#define A2_STRIDE 40
#define B2_STRIDE 40

__global__ __launch_bounds__(256) void gemm2_tc_kernel(
    const float* __restrict__ W2,   // [512, 48]
    const float* __restrict__ bias, // [48]
    __half2* __restrict__ zbuf,     // [M, 24]
    int M)
{
    __shared__ __align__(16) __half As2h[128][A2_STRIDE];
    __shared__ __align__(16) __half Bst[48][B2_STRIDE];

    const int tid = threadIdx.x;
    const int bm = blockIdx.x * 128;

    const int wid = tid >> 5;
    const int lane = tid & 31;
    const int g = lane >> 2;
    const int t = lane & 3;
    const int wm = wid & 3;
    const int wn = wid >> 2;

    const int aRow = tid >> 1;
    const int aCol = (tid & 1) * 16;   // half offset within 32-half chunk
    const int gr = min(bm + aRow, M - 1);

    float acc[2][3][4];
#pragma unroll
    for (int i = 0; i < 2; i++)
#pragma unroll
        for (int j = 0; j < 3; j++)
#pragma unroll
            for (int q = 0; q < 4; q++) acc[i][j][q] = 0.0f;

    uint4 aPre[2];
    float bPre[6];
    aPre[0] = *(const uint4*)(g_hidh + (size_t)gr * D_HID + aCol);
    aPre[1] = *(const uint4*)(g_hidh + (size_t)gr * D_HID + aCol + 8);
#pragma unroll
    for (int j = 0; j < 6; j++) {
        const int idx = tid + 256 * j;
        bPre[j] = W2[(size_t)(idx / 48) * D_OUT + idx % 48];
    }

    for (int k0 = 0; k0 < D_HID; k0 += 32) {
        *(uint4*)&As2h[aRow][aCol]     = aPre[0];
        *(uint4*)&As2h[aRow][aCol + 8] = aPre[1];
#pragma unroll
        for (int j = 0; j < 6; j++) {
            const int idx = tid + 256 * j;
            Bst[idx % 48][idx / 48] = __float2half(bPre[j]);
        }
        __syncthreads();

        if (k0 + 32 < D_HID) {
            aPre[0] = *(const uint4*)(g_hidh + (size_t)gr * D_HID + k0 + 32 + aCol);
            aPre[1] = *(const uint4*)(g_hidh + (size_t)gr * D_HID + k0 + 32 + aCol + 8);
#pragma unroll
            for (int j = 0; j < 6; j++) {
                const int idx = tid + 256 * j;
                bPre[j] = W2[(size_t)(k0 + 32 + idx / 48) * D_OUT + idx % 48];
            }
        }

#pragma unroll
        for (int ks = 0; ks < 2; ks++) {
            const int kb = ks * 16;
            uint32_t af[2][4], bf[3][2];
#pragma unroll
            for (int i = 0; i < 2; i++) {
                const int m = wm * 32 + i * 16 + g;
                af[i][0] = *(const uint32_t*)&As2h[m][kb + 2 * t];
                af[i][1] = *(const uint32_t*)&As2h[m + 8][kb + 2 * t];
                af[i][2] = *(const uint32_t*)&As2h[m][kb + 2 * t + 8];
                af[i][3] = *(const uint32_t*)&As2h[m + 8][kb + 2 * t + 8];
            }
#pragma unroll
            for (int j = 0; j < 3; j++) {
                const int n = wn * 24 + j * 8 + g;
                bf[j][0] = *(const uint32_t*)&Bst[n][kb + 2 * t];
                bf[j][1] = *(const uint32_t*)&Bst[n][kb + 2 * t + 8];
            }
#pragma unroll
            for (int i = 0; i < 2; i++)
#pragma unroll
                for (int j = 0; j < 3; j++)
                    mma_f16(acc[i][j], af[i][0], af[i][1], af[i][2], af[i][3],
                            bf[j][0], bf[j][1]);
        }
        __syncthreads();
    }

#pragma unroll
    for (int i = 0; i < 2; i++) {
        const int r0 = bm + wm * 32 + i * 16 + g;
        const int r1 = r0 + 8;
        const float dv0 = (r0 < M) ? __ldg(g_dinv + r0) : 0.f;
        const float dv1 = (r1 < M) ? __ldg(g_dinv + r1) : 0.f;
#pragma unroll
        for (int j = 0; j < 3; j++) {
            const int gc = wn * 24 + j * 8 + 2 * t;
            const float bz0 = __ldg(bias + gc);
            const float bz1 = __ldg(bias + gc + 1);
            if (r0 < M) {
                float2 v = make_float2(acc[i][j][0] + bz0, acc[i][j][1] + bz1);
                *(float2*)(g_h + (size_t)r0 * D_OUT + gc) = v;
                zbuf[(size_t)r0 * (D_OUT / 2) + gc / 2] =
                    __float22half2_rn(make_float2(dv0 * v.x, dv0 * v.y));
            }
            if (r1 < M) {
                float2 v = make_float2(acc[i][j][2] + bz0, acc[i][j][3] + bz1);
                *(float2*)(g_h + (size_t)r1 * D_OUT + gc) = v;
                zbuf[(size_t)r1 * (D_OUT / 2) + gc / 2] =
                    __float22half2_rn(make_float2(dv1 * v.x, dv1 * v.y));
            }
        }
    }
}

// ---------------------------------------------------------------------------
// Graph preprocessing
// ---------------------------------------------------------------------------
__global__ void convert_idx_kernel(const void* __restrict__ ei_raw) {
    const int* p32 = (const int*)ei_raw;
    bool is64 = true;
#pragma unroll
    for (int i = 0; i < 8; i++) is64 = is64 && (p32[2 * i + 1] == 0);

    int e = blockIdx.x * blockDim.x + threadIdx.x;
    if (e >= N_EDGES) return;
    int s, d;
    if (is64) {
        const long long* p64 = (const long long*)ei_raw;
        s = (int)p64[e];
        d = (int)p64[(size_t)N_EDGES + e];
    } else {
        s = p32[e];
        d = p32[(size_t)N_EDGES + e];
    }
    s = min(max(s, 0), N_NODES - 1);
    d = min(max(d, 0), N_NODES - 1);
    g_src[e] = s;
    g_dst[e] = d;
}

// Fused: zero deg/cursor/buckets + pre-round W1 to tf32.
__global__ void prep_kernel(const float* __restrict__ W1) {
    int i = blockIdx.x * blockDim.x + threadIdx.x;
    if (i < N_NODES) { g_deg[i] = 0; g_cursor[i] = 0; }
    if (i < N_BUCKET) { g_bucket[i] = 0; g_bcur[i] = 0; }
    if (i < W1_ELEMS) g_w1r[i] = __uint_as_float(f2tf32(W1[i]));
}

__global__ void deg_acc_kernel() {
    int e = blockIdx.x * blockDim.x + threadIdx.x;
    if (e < N_EDGES) atomicAdd(&g_deg[g_dst[e]], 1);
}

__global__ __launch_bounds__(256) void blocksum_dinv_kernel() {
    __shared__ int swarp[8];
    const int t = threadIdx.x;
    const int i = blockIdx.x * 256 + t;
    int d = 0;
    if (i < N_NODES) {
        d = g_deg[i];
        g_dinv[i] = rsqrtf((float)(d + 1));   // +1 self-loop
    }
    int v = d;
#pragma unroll
    for (int o = 16; o > 0; o >>= 1) v += __shfl_down_sync(0xffffffffu, v, o);
    if ((t & 31) == 0) swarp[t >> 5] = v;
    __syncthreads();
    if (t == 0) {
        int s = 0;
#pragma unroll
        for (int w = 0; w < 8; w++) s += swarp[w];
        g_bsum[blockIdx.x] = s;
    }
}

__global__ __launch_bounds__(512) void scan_bsums_kernel() {
    __shared__ int sh[512];
    const int t = threadIdx.x;
    sh[t] = (t < NBLK_NODES) ? g_bsum[t] : 0;
    __syncthreads();
#pragma unroll
    for (int off = 1; off < 512; off <<= 1) {
        int v = (t >= off) ? sh[t - off] : 0;
        __syncthreads();
        sh[t] += v;
        __syncthreads();
    }
    if (t < NBLK_NODES) g_bpre[t] = (t == 0) ? 0 : sh[t - 1];
}

__global__ __launch_bounds__(256) void rowptr_kernel() {
    __shared__ int swarp[8];
    const int t = threadIdx.x;
    const int i = blockIdx.x * 256 + t;
    const int lane = t & 31;
    const int w = t >> 5;

    int d = (i < N_NODES) ? g_deg[i] : 0;
    int v = d;
#pragma unroll
    for (int o = 1; o < 32; o <<= 1) {
        int n = __shfl_up_sync(0xffffffffu, v, o);
        if (lane >= o) v += n;
    }
    if (lane == 31) swarp[w] = v;
    __syncthreads();
    if (t == 0) {
        int r = 0;
#pragma unroll
        for (int k = 0; k < 8; k++) { int tmp = swarp[k]; swarp[k] = r; r += tmp; }
    }
    __syncthreads();

    const int excl = g_bpre[blockIdx.x] + swarp[w] + (v - d);
    if (i < N_NODES) {
        g_rowptr[i] = excl;
        if (i == N_NODES - 1) g_rowptr[N_NODES] = excl + d;
    }
}

// Degree histogram (64 buckets) for the counting sort.
__global__ __launch_bounds__(256) void hist_kernel() {
    __shared__ int sh[N_BUCKET];
    const int t = threadIdx.x;
    if (t < N_BUCKET) sh[t] = 0;
    __syncthreads();
    const int i = blockIdx.x * 256 + t;
    if (i < N_NODES) atomicAdd(&sh[min(g_deg[i], N_BUCKET - 1)], 1);
    __syncthreads();
    if (t < N_BUCKET && sh[t] > 0) atomicAdd(&g_bucket[t], sh[t]);
}

// Exclusive scan of 64 bucket counts (1 warp, 2 per thread).
__global__ __launch_bounds__(32) void bucket_scan_kernel() {
    const int t = threadIdx.x;
    const int c0 = g_bucket[2 * t];
    const int c1 = g_bucket[2 * t + 1];
    int s = c0 + c1;
#pragma unroll
    for (int o = 1; o < 32; o <<= 1) {
        int n = __shfl_up_sync(0xffffffffu, s, o);
        if (t >= o) s += n;
    }
    const int excl = s - (c0 + c1);
    g_bstart[2 * t] = excl;
    g_bstart[2 * t + 1] = excl + c0;
}

// Scatter nodes into degree-sorted permutation.
__global__ void perm_scatter_kernel() {
    int i = blockIdx.x * blockDim.x + threadIdx.x;
    if (i >= N_NODES) return;
    const int b = min(g_deg[i], N_BUCKET - 1);
    const int pos = g_bstart[b] + atomicAdd(&g_bcur[b], 1);
    g_perm[pos] = i;
}

__global__ void fill_csr_kernel() {
    int e = blockIdx.x * blockDim.x + threadIdx.x;
    if (e >= N_EDGES) return;
    const int s = g_src[e];
    const int d = g_dst[e];
    const int pos = g_rowptr[d] + atomicAdd(&g_cursor[d], 1);
    g_csri[pos] = s;
}

// ---------------------------------------------------------------------------
// Propagation on z = half2(dinv .* out), 8 threads/node, degree-sorted
// node assignment via g_perm (equal work within each warp).
// ---------------------------------------------------------------------------
__global__ __launch_bounds__(256) void gather_z_kernel(
    const __half2* __restrict__ z, __half2* __restrict__ nxt,
    float* __restrict__ outf, int last)
{
    const int gid = blockIdx.x * 32 + (threadIdx.x >> 3);
    const int lane = threadIdx.x & 7;
    if (gid >= N_NODES) return;
    const int node = __ldg(&g_perm[gid]);

    const int begin = g_rowptr[node];
    const int end   = g_rowptr[node + 1];

    float2 s0 = make_float2(0.f, 0.f);
    float2 s1 = make_float2(0.f, 0.f);
    float2 s2 = make_float2(0.f, 0.f);

    int e = begin;
    for (; e + 2 <= end; e += 2) {
        const int srcA = __ldg(&g_csri[e]);
        const int srcB = __ldg(&g_csri[e + 1]);
        const __half2* pA = z + (size_t)srcA * (D_OUT / 2) + lane;
        const __half2* pB = z + (size_t)srcB * (D_OUT / 2) + lane;
        const float2 a0 = __half22float2(__ldg(pA));
        const float2 a1 = __half22float2(__ldg(pA + 8));
        const float2 a2 = __half22float2(__ldg(pA + 16));
        const float2 b0 = __half22float2(__ldg(pB));
        const float2 b1 = __half22float2(__ldg(pB + 8));
        const float2 b2 = __half22float2(__ldg(pB + 16));
        s0.x += a0.x + b0.x; s0.y += a0.y + b0.y;
        s1.x += a1.x + b1.x; s1.y += a1.y + b1.y;
        s2.x += a2.x + b2.x; s2.y += a2.y + b2.y;
    }
    if (e < end) {
        const int src = __ldg(&g_csri[e]);
        const __half2* p = z + (size_t)src * (D_OUT / 2) + lane;
        const float2 v0 = __half22float2(__ldg(p));
        const float2 v1 = __half22float2(__ldg(p + 8));
        const float2 v2 = __half22float2(__ldg(p + 16));
        s0.x += v0.x; s0.y += v0.y;
        s1.x += v1.x; s1.y += v1.y;
        s2.x += v2.x; s2.y += v2.y;
    }

    {   // self-loop contribution
        const __half2* p = z + (size_t)node * (D_OUT / 2) + lane;
        const float2 v0 = __half22float2(p[0]);
        const float2 v1 = __half22float2(p[8]);
        const float2 v2 = __half22float2(p[16]);
        s0.x += v0.x; s0.y += v0.y;
        s1.x += v1.x; s1.y += v1.y;
        s2.x += v2.x; s2.y += v2.y;
    }

    const float di = g_dinv[node];
    const float* ph = g_h + (size_t)node * D_OUT + 2 * lane;
    const float2 h0 = *(const float2*)(ph);
    const float2 h1 = *(const float2*)(ph + 16);
    const float2 h2 = *(const float2*)(ph + 32);

    const float w = (1.0f - ALPHA) * di;
    float2 o0 = make_float2(w * s0.x + ALPHA * h0.x, w * s0.y + ALPHA * h0.y);
    float2 o1 = make_float2(w * s1.x + ALPHA * h1.x, w * s1.y + ALPHA * h1.y);
    float2 o2 = make_float2(w * s2.x + ALPHA * h2.x, w * s2.y + ALPHA * h2.y);

    if (last) {
        float* po = outf + (size_t)node * D_OUT + 2 * lane;
        *(float2*)(po)      = o0;
        *(float2*)(po + 16) = o1;
        *(float2*)(po + 32) = o2;
    } else {
        __half2* po = nxt + (size_t)node * (D_OUT / 2) + lane;
        po[0]  = __float22half2_rn(make_float2(di * o0.x, di * o0.y));
        po[8]  = __float22half2_rn(make_float2(di * o1.x, di * o1.y));
        po[16] = __float22half2_rn(make_float2(di * o2.x, di * o2.y));
    }
}

// ---------------------------------------------------------------------------
// Launch. Inputs matched by element count. gemm1 stays at launch slot 3.
// ---------------------------------------------------------------------------
extern "C" void kernel_launch(void* const* d_in, const int* in_sizes, int n_in,
                              void* d_out, int out_size)
{
    const void* x = nullptr; const void* ei = nullptr;
    const void* W1 = nullptr; const void* b1 = nullptr;
    const void* W2 = nullptr; const void* b2 = nullptr;

    for (int i = 0; i < n_in; i++) {
        switch (in_sizes[i]) {
            case 25600000: x  = d_in[i]; break;
            case  3200000: ei = d_in[i]; break;
            case   131072: W1 = d_in[i]; break;
            case      512: b1 = d_in[i]; break;
            case    24576: W2 = d_in[i]; break;
            case       48: b2 = d_in[i]; break;
            default: break;
        }
    }
    if (!x)  x  = d_in[0];
    if (!ei) ei = d_in[1];
    if (!W1) W1 = d_in[2];
    if (!b1) b1 = d_in[3];
    if (!W2) W2 = d_in[4];
    if (!b2) b2 = d_in[5];

    float* out = (float*)d_out;
    const int M = N_NODES;

    __half2* zA;  cudaGetSymbolAddress((void**)&zA, g_zA);
    __half2* zB;  cudaGetSymbolAddress((void**)&zB, g_zB);

    static int smem_set = 0;
    if (!smem_set) {
        cudaFuncSetAttribute(gemm1_tc_kernel,
                             cudaFuncAttributeMaxDynamicSharedMemorySize, G1_SMEM);
        smem_set = 1;
    }

    // 0-2: preprocessing that gemm1 doesn't need (+W1 tf32 pre-round)
    convert_idx_kernel<<<(N_EDGES + 255) / 256, 256>>>(ei);
    prep_kernel<<<(W1_ELEMS + 255) / 256, 256>>>((const float*)W1);
    deg_acc_kernel<<<(N_EDGES + 255) / 256, 256>>>();

    // 3: GEMM1 (target of the ncu capture at launch index 3)
    {
        dim3 grid(D_HID / 128, (M + 127) / 128);
        gemm1_tc_kernel<<<grid, 256, G1_SMEM>>>((const float*)x,
                                                (const float*)b1, M);
    }

    // 4-6: full-chip scan -> rowptr (+dinv folded into pass A)
    blocksum_dinv_kernel<<<NBLK_NODES, 256>>>();
    scan_bsums_kernel<<<1, 512>>>();
    rowptr_kernel<<<NBLK_NODES, 256>>>();

    // 7-9: degree counting sort -> g_perm (gather load balance)
    hist_kernel<<<NBLK_NODES, 256>>>();
    bucket_scan_kernel<<<1, 32>>>();
    perm_scatter_kernel<<<NBLK_NODES, 256>>>();

    // 10: CSR fill (src only)
    fill_csr_kernel<<<(N_EDGES + 255) / 256, 256>>>();

    // 11: GEMM2 (writes g_h = h fp32 and zA = half2(dinv*h))
    {
        dim3 grid((M + 127) / 128);
        gemm2_tc_kernel<<<grid, 256>>>((const float*)W2, (const float*)b2, zA, M);
    }

    // 12..21: 10 propagation steps on fp16 z; last step emits fp32 out.
    const int gblocks = (N_NODES + 31) / 32;
    __half2* cur = zA;
    __half2* nxt = zB;
    for (int s = 0; s < K_STEPS; s++) {
        gather_z_kernel<<<gblocks, 256>>>(cur, nxt, out, s == K_STEPS - 1 ? 1 : 0);
        __half2* tmp = cur; cur = nxt; nxt = tmp;
    }
}

// round 11
// speedup vs baseline: 1.0349x; 1.0349x over previous
#include <cuda_runtime.h>
#include <cuda_fp16.h>
#include <cstdint>

// ---------------------------------------------------------------------------
// Problem constants (fixed by the dataset)
// ---------------------------------------------------------------------------
#define N_NODES 100000
#define N_EDGES 1600000
#define D_IN    256
#define D_HID   512
#define D_OUT   48
#define K_STEPS 10
#define ALPHA   0.1f

#define NBLK_NODES ((N_NODES + 255) / 256)   // 391
#define W1_ELEMS  (D_IN * D_HID)             // 131072
#define W2_ELEMS  (D_HID * D_OUT)            // 24576

// ---------------------------------------------------------------------------
// Scratch (static __device__ arrays; no allocation allowed)
// ---------------------------------------------------------------------------
__device__ __align__(16) __half g_hidh[(size_t)N_NODES * D_HID];  // fp16 hid
__device__ __align__(16) float g_h[(size_t)N_NODES * D_OUT];
__device__ __align__(16) float g_w1r[W1_ELEMS];                   // tf32-rounded W1
__device__ __align__(16) __half g_w2t[W2_ELEMS];                  // W2^T fp16 [48][512]
__device__ __align__(16) __half2 g_zA[(size_t)N_NODES * (D_OUT / 2)];
__device__ __align__(16) __half2 g_zB[(size_t)N_NODES * (D_OUT / 2)];
__device__ float g_dinv[N_NODES];
__device__ int   g_deg[N_NODES];
__device__ int   g_cursor[N_NODES];
__device__ int   g_rowptr[N_NODES + 1];
__device__ int   g_bsum[NBLK_NODES];
__device__ int   g_bpre[NBLK_NODES];
__device__ int   g_src[N_EDGES];
__device__ int   g_dst[N_EDGES];
__device__ int   g_csri[N_EDGES];     // CSR: src index only (norm folded into z)

// ---------------------------------------------------------------------------
// mma helpers
// ---------------------------------------------------------------------------
__device__ __forceinline__ uint32_t f2tf32(float f) {
    uint32_t u;
    asm("cvt.rna.tf32.f32 %0, %1;" : "=r"(u) : "f"(f));
    return u;
}

__device__ __forceinline__ void mma_tf32(float* c,
                                         uint32_t a0, uint32_t a1,
                                         uint32_t a2, uint32_t a3,
                                         uint32_t b0, uint32_t b1) {
    asm volatile(
        "mma.sync.aligned.m16n8k8.row.col.f32.tf32.tf32.f32 "
        "{%0,%1,%2,%3}, {%4,%5,%6,%7}, {%8,%9}, {%0,%1,%2,%3};"
        : "+f"(c[0]), "+f"(c[1]), "+f"(c[2]), "+f"(c[3])
        : "r"(a0), "r"(a1), "r"(a2), "r"(a3), "r"(b0), "r"(b1));
}

__device__ __forceinline__ void mma_f16(float* c,
                                        uint32_t a0, uint32_t a1,
                                        uint32_t a2, uint32_t a3,
                                        uint32_t b0, uint32_t b1) {
    asm volatile(
        "mma.sync.aligned.m16n8k16.row.col.f32.f16.f16.f32 "
        "{%0,%1,%2,%3}, {%4,%5,%6,%7}, {%8,%9}, {%0,%1,%2,%3};"
        : "+f"(c[0]), "+f"(c[1]), "+f"(c[2]), "+f"(c[3])
        : "r"(a0), "r"(a1), "r"(a2), "r"(a3), "r"(b0), "r"(b1));
}

#define CP_ASYNC_16(dst_u32, src_ptr) \
    asm volatile("cp.async.cg.shared.global [%0], [%1], 16;" \
                 :: "r"(dst_u32), "l"(src_ptr))
#define CP_COMMIT() asm volatile("cp.async.commit_group;")
#define CP_WAIT(N)  asm volatile("cp.async.wait_group %0;" :: "n"(N))

// ---------------------------------------------------------------------------
// GEMM1: g_hidh = half(relu(x @ W1 + b1)), tf32 tensor cores. (as R9/R10)
// ---------------------------------------------------------------------------
#define AS_STRIDE 20
#define BS_STRIDE 136
#define AS_STAGE (128 * AS_STRIDE)
#define BS_STAGE (16 * BS_STRIDE)
#define G1_SMEM ((3 * AS_STAGE + 3 * BS_STAGE) * 4)   // 56832 bytes
#define N_CHUNK (D_IN / 16)                 // 16

__global__ __launch_bounds__(256, 2) void gemm1_tc_kernel(
    const float* __restrict__ A,    // [M, 256]
    const float* __restrict__ bias, // [512]
    int M)
{
    extern __shared__ float smem[];
    float* AsB = smem;
    float* BsB = smem + 3 * AS_STAGE;

    const int tid = threadIdx.x;
    const int bn = blockIdx.x * 128;
    const int bm = blockIdx.y * 128;

    const int wid = tid >> 5;
    const int lane = tid & 31;
    const int g = lane >> 2;
    const int t = lane & 3;
    const int wm = wid & 1;
    const int wn = wid >> 1;

    float acc[4][4][4];
#pragma unroll
    for (int i = 0; i < 4; i++)
#pragma unroll
        for (int j = 0; j < 4; j++)
#pragma unroll
            for (int q = 0; q < 4; q++) acc[i][j][q] = 0.0f;

    uint32_t aDst[2], bDst[2];
    const float* aSrc[2];
    const float* bSrc[2];
    {
        const uint32_t asBase = (uint32_t)__cvta_generic_to_shared(AsB);
        const uint32_t bsBase = (uint32_t)__cvta_generic_to_shared(BsB);
#pragma unroll
        for (int q = 0; q < 2; q++) {
            const int idx = tid + 256 * q;
            const int ar = idx >> 2;
            const int ac = (idx & 3) * 4;
            aDst[q] = asBase + (ar * AS_STRIDE + ac) * 4;
            const int gr = min(bm + ar, M - 1);
            aSrc[q] = A + (size_t)gr * D_IN + ac;
            const int br = idx >> 5;
            const int bc = (idx & 31) * 4;
            bDst[q] = bsBase + (br * BS_STRIDE + bc) * 4;
            bSrc[q] = g_w1r + (size_t)br * D_HID + bn + bc;
        }
    }

#pragma unroll
    for (int q = 0; q < 2; q++) {
        CP_ASYNC_16(aDst[q], aSrc[q]);
        CP_ASYNC_16(bDst[q], bSrc[q]);
    }
    CP_COMMIT();
#pragma unroll
    for (int q = 0; q < 2; q++) {
        CP_ASYNC_16(aDst[q] + AS_STAGE * 4, aSrc[q] + 16);
        CP_ASYNC_16(bDst[q] + BS_STAGE * 4, bSrc[q] + (size_t)16 * D_HID);
    }
    CP_COMMIT();

    int stC = 0;
    for (int ch = 0; ch < N_CHUNK; ch++) {
        if (ch < N_CHUNK - 1) { CP_WAIT(1); } else { CP_WAIT(0); }
        __syncthreads();

        const float* As = AsB + stC * AS_STAGE;
        const float* Bs = BsB + stC * BS_STAGE;
#pragma unroll
        for (int ks = 0; ks < 2; ks++) {
            const int kb = ks * 8;
            uint32_t af[4][4], bf[4][2];
#pragma unroll
            for (int i = 0; i < 4; i++) {
                const int m = wm * 64 + i * 16 + g;
                af[i][0] = f2tf32(As[m * AS_STRIDE + kb + t]);
                af[i][1] = f2tf32(As[(m + 8) * AS_STRIDE + kb + t]);
                af[i][2] = f2tf32(As[m * AS_STRIDE + kb + t + 4]);
                af[i][3] = f2tf32(As[(m + 8) * AS_STRIDE + kb + t + 4]);
            }
#pragma unroll
            for (int j = 0; j < 4; j++) {
                const int n = wn * 32 + j * 8 + g;
                bf[j][0] = __float_as_uint(Bs[(kb + t) * BS_STRIDE + n]);
                bf[j][1] = __float_as_uint(Bs[(kb + t + 4) * BS_STRIDE + n]);
            }
#pragma unroll
            for (int i = 0; i < 4; i++)
#pragma unroll
                for (int j = 0; j < 4; j++)
                    mma_tf32(acc[i][j], af[i][0], af[i][1], af[i][2], af[i][3],
                             bf[j][0], bf[j][1]);
        }

        if (ch + 2 < N_CHUNK) {
            const int stP = (stC + 2 >= 3) ? stC - 1 : stC + 2;
            const int ko = (ch + 2) * 16;
#pragma unroll
            for (int q = 0; q < 2; q++) {
                CP_ASYNC_16(aDst[q] + stP * AS_STAGE * 4, aSrc[q] + ko);
                CP_ASYNC_16(bDst[q] + stP * BS_STAGE * 4, bSrc[q] + (size_t)ko * D_HID);
            }
            CP_COMMIT();
        }
        stC = (stC + 1 == 3) ? 0 : stC + 1;
    }

    // epilogue: bias + relu -> fp16 store
#pragma unroll
    for (int i = 0; i < 4; i++) {
        const int r0 = bm + wm * 64 + i * 16 + g;
        const int r1 = r0 + 8;
#pragma unroll
        for (int j = 0; j < 4; j++) {
            const int gc = bn + wn * 32 + j * 8 + 2 * t;
            const float bz0 = __ldg(bias + gc);
            const float bz1 = __ldg(bias + gc + 1);
            if (r0 < M) {
                *(__half2*)(g_hidh + (size_t)r0 * D_HID + gc) =
                    __float22half2_rn(make_float2(fmaxf(acc[i][j][0] + bz0, 0.f),
                                                  fmaxf(acc[i][j][1] + bz1, 0.f)));
            }
            if (r1 < M) {
                *(__half2*)(g_hidh + (size_t)r1 * D_HID + gc) =
                    __float22half2_rn(make_float2(fmaxf(acc[i][j][2] + bz0, 0.f),
                                                  fmaxf(acc[i][j][3] + bz1, 0.f)));
            }
        }
    }
}

// ---------------------------------------------------------------------------
// GEMM2: h = hid(fp16) @ W2 + b2, fp16 m16n8k16 mma, fp32 accum.
// A staged in smem ([m][k] stride 40 halves, conflict-free); B fragments
// loaded directly from pre-transposed fp16 W2T (48x512, L1-resident).
// Epilogue: g_h = h (fp32); zbuf = half2(dinv * h).
// ---------------------------------------------------------------------------
#define A2_STRIDE 40

__global__ __launch_bounds__(256) void gemm2_tc_kernel(
    const float* __restrict__ bias, // [48]
    __half2* __restrict__ zbuf,     // [M, 24]
    int M)
{
    __shared__ __align__(16) __half As2h[128][A2_STRIDE];

    const int tid = threadIdx.x;
    const int bm = blockIdx.x * 128;

    const int wid = tid >> 5;
    const int lane = tid & 31;
    const int g = lane >> 2;
    const int t = lane & 3;
    const int wm = wid & 3;
    const int wn = wid >> 2;

    const int aRow = tid >> 1;
    const int aCol = (tid & 1) * 16;   // half offset within 32-half chunk
    const int gr = min(bm + aRow, M - 1);

    float acc[2][3][4];
#pragma unroll
    for (int i = 0; i < 2; i++)
#pragma unroll
        for (int j = 0; j < 3; j++)
#pragma unroll
            for (int q = 0; q < 4; q++) acc[i][j][q] = 0.0f;

    uint4 aPre[2];
    aPre[0] = *(const uint4*)(g_hidh + (size_t)gr * D_HID + aCol);
    aPre[1] = *(const uint4*)(g_hidh + (size_t)gr * D_HID + aCol + 8);

    for (int k0 = 0; k0 < D_HID; k0 += 32) {
        *(uint4*)&As2h[aRow][aCol]     = aPre[0];
        *(uint4*)&As2h[aRow][aCol + 8] = aPre[1];
        __syncthreads();

        if (k0 + 32 < D_HID) {
            aPre[0] = *(const uint4*)(g_hidh + (size_t)gr * D_HID + k0 + 32 + aCol);
            aPre[1] = *(const uint4*)(g_hidh + (size_t)gr * D_HID + k0 + 32 + aCol + 8);
        }

#pragma unroll
        for (int ks = 0; ks < 2; ks++) {
            const int kb = ks * 16;
            uint32_t af[2][4], bf[3][2];
#pragma unroll
            for (int i = 0; i < 2; i++) {
                const int m = wm * 32 + i * 16 + g;
                af[i][0] = *(const uint32_t*)&As2h[m][kb + 2 * t];
                af[i][1] = *(const uint32_t*)&As2h[m + 8][kb + 2 * t];
                af[i][2] = *(const uint32_t*)&As2h[m][kb + 2 * t + 8];
                af[i][3] = *(const uint32_t*)&As2h[m + 8][kb + 2 * t + 8];
            }
#pragma unroll
            for (int j = 0; j < 3; j++) {
                const int n = wn * 24 + j * 8 + g;
                const __half* wp = g_w2t + (size_t)n * D_HID + k0 + kb + 2 * t;
                bf[j][0] = __ldg((const uint32_t*)wp);
                bf[j][1] = __ldg((const uint32_t*)(wp + 8));
            }
#pragma unroll
            for (int i = 0; i < 2; i++)
#pragma unroll
                for (int j = 0; j < 3; j++)
                    mma_f16(acc[i][j], af[i][0], af[i][1], af[i][2], af[i][3],
                            bf[j][0], bf[j][1]);
        }
        __syncthreads();
    }

#pragma unroll
    for (int i = 0; i < 2; i++) {
        const int r0 = bm + wm * 32 + i * 16 + g;
        const int r1 = r0 + 8;
        const float dv0 = (r0 < M) ? __ldg(g_dinv + r0) : 0.f;
        const float dv1 = (r1 < M) ? __ldg(g_dinv + r1) : 0.f;
#pragma unroll
        for (int j = 0; j < 3; j++) {
            const int gc = wn * 24 + j * 8 + 2 * t;
            const float bz0 = __ldg(bias + gc);
            const float bz1 = __ldg(bias + gc + 1);
            if (r0 < M) {
                float2 v = make_float2(acc[i][j][0] + bz0, acc[i][j][1] + bz1);
                *(float2*)(g_h + (size_t)r0 * D_OUT + gc) = v;
                zbuf[(size_t)r0 * (D_OUT / 2) + gc / 2] =
                    __float22half2_rn(make_float2(dv0 * v.x, dv0 * v.y));
            }
            if (r1 < M) {
                float2 v = make_float2(acc[i][j][2] + bz0, acc[i][j][3] + bz1);
                *(float2*)(g_h + (size_t)r1 * D_OUT + gc) = v;
                zbuf[(size_t)r1 * (D_OUT / 2) + gc / 2] =
                    __float22half2_rn(make_float2(dv1 * v.x, dv1 * v.y));
            }
        }
    }
}

// ---------------------------------------------------------------------------
// Graph preprocessing
// ---------------------------------------------------------------------------
__global__ void convert_idx_kernel(const void* __restrict__ ei_raw) {
    const int* p32 = (const int*)ei_raw;
    bool is64 = true;
#pragma unroll
    for (int i = 0; i < 8; i++) is64 = is64 && (p32[2 * i + 1] == 0);

    int e = blockIdx.x * blockDim.x + threadIdx.x;
    if (e >= N_EDGES) return;
    int s, d;
    if (is64) {
        const long long* p64 = (const long long*)ei_raw;
        s = (int)p64[e];
        d = (int)p64[(size_t)N_EDGES + e];
    } else {
        s = p32[e];
        d = p32[(size_t)N_EDGES + e];
    }
    s = min(max(s, 0), N_NODES - 1);
    d = min(max(d, 0), N_NODES - 1);
    g_src[e] = s;
    g_dst[e] = d;
}

// Fused: zero deg/cursor + pre-round W1 (tf32) + transpose W2 to fp16.
__global__ void prep_kernel(const float* __restrict__ W1,
                            const float* __restrict__ W2) {
    int i = blockIdx.x * blockDim.x + threadIdx.x;
    if (i < N_NODES) { g_deg[i] = 0; g_cursor[i] = 0; }
    if (i < W1_ELEMS) g_w1r[i] = __uint_as_float(f2tf32(W1[i]));
    if (i < W2_ELEMS) {
        const int n = i % D_OUT;
        const int k = i / D_OUT;
        g_w2t[(size_t)n * D_HID + k] = __float2half(W2[i]);
    }
}

__global__ void deg_acc_kernel() {
    int e = blockIdx.x * blockDim.x + threadIdx.x;
    if (e < N_EDGES) atomicAdd(&g_deg[g_dst[e]], 1);
}

__global__ __launch_bounds__(256) void blocksum_dinv_kernel() {
    __shared__ int swarp[8];
    const int t = threadIdx.x;
    const int i = blockIdx.x * 256 + t;
    int d = 0;
    if (i < N_NODES) {
        d = g_deg[i];
        g_dinv[i] = rsqrtf((float)(d + 1));   // +1 self-loop
    }
    int v = d;
#pragma unroll
    for (int o = 16; o > 0; o >>= 1) v += __shfl_down_sync(0xffffffffu, v, o);
    if ((t & 31) == 0) swarp[t >> 5] = v;
    __syncthreads();
    if (t == 0) {
        int s = 0;
#pragma unroll
        for (int w = 0; w < 8; w++) s += swarp[w];
        g_bsum[blockIdx.x] = s;
    }
}

__global__ __launch_bounds__(512) void scan_bsums_kernel() {
    __shared__ int sh[512];
    const int t = threadIdx.x;
    sh[t] = (t < NBLK_NODES) ? g_bsum[t] : 0;
    __syncthreads();
#pragma unroll
    for (int off = 1; off < 512; off <<= 1) {
        int v = (t >= off) ? sh[t - off] : 0;
        __syncthreads();
        sh[t] += v;
        __syncthreads();
    }
    if (t < NBLK_NODES) g_bpre[t] = (t == 0) ? 0 : sh[t - 1];
}

__global__ __launch_bounds__(256) void rowptr_kernel() {
    __shared__ int swarp[8];
    const int t = threadIdx.x;
    const int i = blockIdx.x * 256 + t;
    const int lane = t & 31;
    const int w = t >> 5;

    int d = (i < N_NODES) ? g_deg[i] : 0;
    int v = d;
#pragma unroll
    for (int o = 1; o < 32; o <<= 1) {
        int n = __shfl_up_sync(0xffffffffu, v, o);
        if (lane >= o) v += n;
    }
    if (lane == 31) swarp[w] = v;
    __syncthreads();
    if (t == 0) {
        int r = 0;
#pragma unroll
        for (int k = 0; k < 8; k++) { int tmp = swarp[k]; swarp[k] = r; r += tmp; }
    }
    __syncthreads();

    const int excl = g_bpre[blockIdx.x] + swarp[w] + (v - d);
    if (i < N_NODES) {
        g_rowptr[i] = excl;
        if (i == N_NODES - 1) g_rowptr[N_NODES] = excl + d;
    }
}

__global__ void fill_csr_kernel() {
    int e = blockIdx.x * blockDim.x + threadIdx.x;
    if (e >= N_EDGES) return;
    const int s = g_src[e];
    const int d = g_dst[e];
    const int pos = g_rowptr[d] + atomicAdd(&g_cursor[d], 1);
    g_csri[pos] = s;
}

// ---------------------------------------------------------------------------
// Propagation on z = half2(dinv .* out), 8 threads/node (sequential nodes,
// coalesced). Lanes 0-5 each own a 16B slice of the 96B row and load it with
// ONE uint4 per edge (4x fewer LDG instructions than half2 loads).
// ---------------------------------------------------------------------------
__global__ __launch_bounds__(256) void gather_z_kernel(
    const __half2* __restrict__ z, __half2* __restrict__ nxt,
    float* __restrict__ outf, int last)
{
    const int node = blockIdx.x * 32 + (threadIdx.x >> 3);
    const int lane = threadIdx.x & 7;
    if (node >= N_NODES || lane >= 6) return;   // lanes 6,7 idle

    const int begin = __ldg(&g_rowptr[node]);
    const int end   = __ldg(&g_rowptr[node + 1]);

    const char* zb = (const char*)z;
    const size_t lOff = (size_t)lane * 16;

    float2 s0 = make_float2(0.f, 0.f);
    float2 s1 = make_float2(0.f, 0.f);
    float2 s2 = make_float2(0.f, 0.f);
    float2 s3 = make_float2(0.f, 0.f);

    int e = begin;
    for (; e + 2 <= end; e += 2) {
        const int srcA = __ldg(&g_csri[e]);
        const int srcB = __ldg(&g_csri[e + 1]);
        const uint4 va = __ldg((const uint4*)(zb + (size_t)srcA * 96 + lOff));
        const uint4 vb = __ldg((const uint4*)(zb + (size_t)srcB * 96 + lOff));
        const __half2* ha = (const __half2*)&va;
        const __half2* hb = (const __half2*)&vb;
        float2 f;
        f = __half22float2(ha[0]); s0.x += f.x; s0.y += f.y;
        f = __half22float2(ha[1]); s1.x += f.x; s1.y += f.y;
        f = __half22float2(ha[2]); s2.x += f.x; s2.y += f.y;
        f = __half22float2(ha[3]); s3.x += f.x; s3.y += f.y;
        f = __half22float2(hb[0]); s0.x += f.x; s0.y += f.y;
        f = __half22float2(hb[1]); s1.x += f.x; s1.y += f.y;
        f = __half22float2(hb[2]); s2.x += f.x; s2.y += f.y;
        f = __half22float2(hb[3]); s3.x += f.x; s3.y += f.y;
    }
    if (e < end) {
        const int src = __ldg(&g_csri[e]);
        const uint4 v = __ldg((const uint4*)(zb + (size_t)src * 96 + lOff));
        const __half2* hv = (const __half2*)&v;
        float2 f;
        f = __half22float2(hv[0]); s0.x += f.x; s0.y += f.y;
        f = __half22float2(hv[1]); s1.x += f.x; s1.y += f.y;
        f = __half22float2(hv[2]); s2.x += f.x; s2.y += f.y;
        f = __half22float2(hv[3]); s3.x += f.x; s3.y += f.y;
    }

    {   // self-loop contribution
        const uint4 v = *(const uint4*)(zb + (size_t)node * 96 + lOff);
        const __half2* hv = (const __half2*)&v;
        float2 f;
        f = __half22float2(hv[0]); s0.x += f.x; s0.y += f.y;
        f = __half22float2(hv[1]); s1.x += f.x; s1.y += f.y;
        f = __half22float2(hv[2]); s2.x += f.x; s2.y += f.y;
        f = __half22float2(hv[3]); s3.x += f.x; s3.y += f.y;
    }

    const float di = __ldg(&g_dinv[node]);
    const float* ph = g_h + (size_t)node * D_OUT + lane * 8;
    const float4 hA = *(const float4*)(ph);
    const float4 hB = *(const float4*)(ph + 4);

    const float w = (1.0f - ALPHA) * di;
    float4 oA, oB;
    oA.x = w * s0.x + ALPHA * hA.x;  oA.y = w * s0.y + ALPHA * hA.y;
    oA.z = w * s1.x + ALPHA * hA.z;  oA.w = w * s1.y + ALPHA * hA.w;
    oB.x = w * s2.x + ALPHA * hB.x;  oB.y = w * s2.y + ALPHA * hB.y;
    oB.z = w * s3.x + ALPHA * hB.z;  oB.w = w * s3.y + ALPHA * hB.w;

    if (last) {
        float* po = outf + (size_t)node * D_OUT + lane * 8;
        *(float4*)(po)     = oA;
        *(float4*)(po + 4) = oB;
    } else {
        uint4 pk;
        __half2* hp = (__half2*)&pk;
        hp[0] = __float22half2_rn(make_float2(di * oA.x, di * oA.y));
        hp[1] = __float22half2_rn(make_float2(di * oA.z, di * oA.w));
        hp[2] = __float22half2_rn(make_float2(di * oB.x, di * oB.y));
        hp[3] = __float22half2_rn(make_float2(di * oB.z, di * oB.w));
        *(uint4*)((char*)nxt + (size_t)node * 96 + lOff) = pk;
    }
}

// ---------------------------------------------------------------------------
// Launch. Inputs matched by element count. gemm1 stays at launch slot 3.
// ---------------------------------------------------------------------------
extern "C" void kernel_launch(void* const* d_in, const int* in_sizes, int n_in,
                              void* d_out, int out_size)
{
    const void* x = nullptr; const void* ei = nullptr;
    const void* W1 = nullptr; const void* b1 = nullptr;
    const void* W2 = nullptr; const void* b2 = nullptr;

    for (int i = 0; i < n_in; i++) {
        switch (in_sizes[i]) {
            case 25600000: x  = d_in[i]; break;
            case  3200000: ei = d_in[i]; break;
            case   131072: W1 = d_in[i]; break;
            case      512: b1 = d_in[i]; break;
            case    24576: W2 = d_in[i]; break;
            case       48: b2 = d_in[i]; break;
            default: break;
        }
    }
    if (!x)  x  = d_in[0];
    if (!ei) ei = d_in[1];
    if (!W1) W1 = d_in[2];
    if (!b1) b1 = d_in[3];
    if (!W2) W2 = d_in[4];
    if (!b2) b2 = d_in[5];

    float* out = (float*)d_out;
    const int M = N_NODES;

    __half2* zA;  cudaGetSymbolAddress((void**)&zA, g_zA);
    __half2* zB;  cudaGetSymbolAddress((void**)&zB, g_zB);

    static int smem_set = 0;
    if (!smem_set) {
        cudaFuncSetAttribute(gemm1_tc_kernel,
                             cudaFuncAttributeMaxDynamicSharedMemorySize, G1_SMEM);
        smem_set = 1;
    }

    // 0-2: preprocessing that gemm1 doesn't need (+W1 round, +W2 transpose)
    convert_idx_kernel<<<(N_EDGES + 255) / 256, 256>>>(ei);
    prep_kernel<<<(W1_ELEMS + 255) / 256, 256>>>((const float*)W1,
                                                 (const float*)W2);
    deg_acc_kernel<<<(N_EDGES + 255) / 256, 256>>>();

    // 3: GEMM1 (target of the ncu capture at launch index 3)
    {
        dim3 grid(D_HID / 128, (M + 127) / 128);
        gemm1_tc_kernel<<<grid, 256, G1_SMEM>>>((const float*)x,
                                                (const float*)b1, M);
    }

    // 4-6: full-chip scan -> rowptr (+dinv folded into pass A)
    blocksum_dinv_kernel<<<NBLK_NODES, 256>>>();
    scan_bsums_kernel<<<1, 512>>>();
    rowptr_kernel<<<NBLK_NODES, 256>>>();

    // 7: CSR fill (src only)
    fill_csr_kernel<<<(N_EDGES + 255) / 256, 256>>>();

    // 8: GEMM2 (writes g_h = h fp32 and zA = half2(dinv*h))
    {
        dim3 grid((M + 127) / 128);
        gemm2_tc_kernel<<<grid, 256>>>((const float*)b2, zA, M);
    }

    // 9..18: 10 propagation steps on fp16 z; last step emits fp32 out.
    const int gblocks = (N_NODES + 31) / 32;
    __half2* cur = zA;
    __half2* nxt = zB;
    for (int s = 0; s < K_STEPS; s++) {
        gather_z_kernel<<<gblocks, 256>>>(cur, nxt, out, s == K_STEPS - 1 ? 1 : 0);
        __half2* tmp = cur; cur = nxt; nxt = tmp;
    }
}